// round 14
// baseline (speedup 1.0000x reference)
#include <cuda_runtime.h>
#include <cuda_fp16.h>
#include <cstdint>
#include <math.h>

#define BB 256
#define TT 40
#define DD 100
#define D2 200
#define NNODE 200000
#define NTYPE 1000
#define NOUT 199999   // N_NODE - 1
#define KP 256        // padded K layout for phase 2

// device-global scratch (no allocation allowed)
__device__ __align__(16) __half g_emb16[(size_t)NNODE * 128];   // 51.2 MB
__device__ __align__(16) __half g_embt16[(size_t)NTYPE * 128];  // 256 KB
__device__ __align__(16) __half g_ma16[BB * KP];                // 128 KB

// ---------------------------------------------------------------------------
// helpers
// ---------------------------------------------------------------------------
__device__ __forceinline__ void mma_f16(float d[4],
                                        uint32_t a0, uint32_t a1, uint32_t a2, uint32_t a3,
                                        uint32_t b0, uint32_t b1) {
    asm volatile(
        "mma.sync.aligned.m16n8k16.row.col.f32.f16.f16.f32 "
        "{%0,%1,%2,%3}, {%4,%5,%6,%7}, {%8,%9}, {%0,%1,%2,%3};\n"
        : "+f"(d[0]), "+f"(d[1]), "+f"(d[2]), "+f"(d[3])
        : "r"(a0), "r"(a1), "r"(a2), "r"(a3), "r"(b0), "r"(b1));
}

__device__ __forceinline__ void ldsm_x4(uint32_t& r0, uint32_t& r1,
                                        uint32_t& r2, uint32_t& r3, uint32_t addr) {
    asm volatile("ldmatrix.sync.aligned.m8n8.x4.shared.b16 {%0,%1,%2,%3}, [%4];"
                 : "=r"(r0), "=r"(r1), "=r"(r2), "=r"(r3) : "r"(addr));
}

__device__ __forceinline__ void cp16(uint32_t dst, const void* src) {
    asm volatile("cp.async.cg.shared.global [%0], [%1], 16;"
                 :: "r"(dst), "l"(src) : "memory");
}
__device__ __forceinline__ void cp_commit() {
    asm volatile("cp.async.commit_group;" ::: "memory");
}
template <int N>
__device__ __forceinline__ void cp_wait() {
    asm volatile("cp.async.wait_group %0;" :: "n"(N) : "memory");
}

__device__ __forceinline__ uint4 h8_of(float4 a, float4 b) {
    __half2 h0 = __float22half2_rn(make_float2(a.x, a.y));
    __half2 h1 = __float22half2_rn(make_float2(a.z, a.w));
    __half2 h2 = __float22half2_rn(make_float2(b.x, b.y));
    __half2 h3 = __float22half2_rn(make_float2(b.z, b.w));
    uint4 u;
    u.x = *reinterpret_cast<uint32_t*>(&h0);
    u.y = *reinterpret_cast<uint32_t*>(&h1);
    u.z = *reinterpret_cast<uint32_t*>(&h2);
    u.w = *reinterpret_cast<uint32_t*>(&h3);
    return u;
}

// ---------------------------------------------------------------------------
// fused0: CTAs [0,256) = phase1 (one batch element each, 512 threads);
//         CTAs [256, 256+NPREP) = prep (fp32 -> fp16 padded table copies).
// Independent work; fusing lets prep's DRAM traffic hide under phase1 compute.
// ---------------------------------------------------------------------------
#define EMB_UNITS (NNODE * 16)
#define EMBT_UNITS (NTYPE * 16)
#define TOT_UNITS (EMB_UNITS + EMBT_UNITS)
#define NPREP ((TOT_UNITS + 1023) / 1024)

__global__ __launch_bounds__(512) void fused0_kernel(
    const float* __restrict__ re,     // [B,U,D]
    const float* __restrict__ ret,    // [B,U,D]
    const float* __restrict__ mask,   // [B,T]
    const float* __restrict__ maskt,  // [B,T]
    const int*   __restrict__ alias,  // [B,T]
    const int*   __restrict__ aliast, // [B,T]
    const float* __restrict__ w1,     // [2D,2D]
    const float* __restrict__ w2,     // [2D,2D]
    const float* __restrict__ w3,     // [2D,2D]
    const float* __restrict__ v,      // [2D]
    const float* __restrict__ bias,   // [2D]
    const float* __restrict__ emb,    // [N_NODE, 100]
    const float* __restrict__ embt)   // [N_TYPE, 100]
{
    const int tid = threadIdx.x;

    if (blockIdx.x >= BB) {
        // ---------------- prep path ----------------
        const int base = (blockIdx.x - BB) * 1024;
        const float4 z = make_float4(0.f, 0.f, 0.f, 0.f);
#pragma unroll
        for (int i = 0; i < 2; i++) {
            int uid = base + tid + i * 512;
            if (uid < EMB_UNITS) {
                int row = uid >> 4, u = uid & 15;
                int fb = 8 * u;
                const float4* src = (const float4*)(emb + (size_t)row * DD);
                float4 f0 = (fb < DD) ? src[fb >> 2] : z;
                float4 f1 = (fb + 4 < DD) ? src[(fb >> 2) + 1] : z;
                *(uint4*)(g_emb16 + (size_t)row * 128 + fb) = h8_of(f0, f1);
            } else if (uid < TOT_UNITS) {
                int t = uid - EMB_UNITS;
                int row = t >> 4, u = t & 15;
                int fb = 8 * u;
                const float4* src = (const float4*)(embt + (size_t)row * DD);
                float4 f0 = (fb < DD) ? src[fb >> 2] : z;
                float4 f1 = (fb + 4 < DD) ? src[(fb >> 2) + 1] : z;
                *(uint4*)(g_embt16 + (size_t)row * 128 + fb) = h8_of(f0, f1);
            }
        }
        return;
    }

    // ---------------- phase1 path ----------------
    extern __shared__ float sm1[];
    float* sh    = sm1;            // [40][200]
    float* cbuf  = sm1 + 8000;     // [40][200]
    float* coefs = sm1 + 16000;    // [40]
    float* svec  = sm1 + 16040;    // [200]
    float* lastv = sm1 + 16240;    // [200]
    __shared__ int sa[TT], sat[TT], slast[2];

    const int b = blockIdx.x;
    const int half = tid >> 8;      // 0: t 0..19, 1: t 20..39
    const int j = tid & 255;
    const int warp = tid >> 5;
    const int lane = tid & 31;

    if (tid < KP) g_ma16[b * KP + tid] = __float2half(0.f);

    if (tid < TT) {
        sa[tid]  = alias[b * TT + tid];
        sat[tid] = aliast[b * TT + tid];
    }
    if (tid == 0) {
        float s = 0.f, st = 0.f;
        for (int t = 0; t < TT; t++) { s += mask[b * TT + t]; st += maskt[b * TT + t]; }
        int rm  = (int)(s  + 0.5f); rm  = rm  < 1 ? 1 : (rm  > TT ? TT : rm);
        int rmt = (int)(st + 0.5f); rmt = rmt < 1 ? 1 : (rmt > TT ? TT : rmt);
        slast[0] = alias[b * TT + rm - 1];
        slast[1] = aliast[b * TT + rmt - 1];
    }
    __syncthreads();

    for (int idx = tid; idx < TT * D2; idx += 512) {
        int t = idx / D2, k = idx - t * D2;
        sh[idx] = (k < DD) ? re[(b * TT + sa[t]) * DD + k]
                           : ret[(b * TT + sat[t]) * DD + (k - DD)];
    }
    if (tid < D2) {
        lastv[tid] = (tid < DD) ? re[(b * TT + slast[0]) * DD + tid]
                                : ret[(b * TT + slast[1]) * DD + (tid - DD)];
    }
    __syncthreads();

    float lpj = 0.f;
    if (j < D2) {
        for (int k = 0; k < D2; k++) lpj += lastv[k] * w1[k * D2 + j];
    }

    if (j < D2) {
        const int tb = half * 20;
        float acc[20];
#pragma unroll
        for (int tt = 0; tt < 20; tt++) acc[tt] = 0.f;
        for (int k = 0; k < D2; k += 4) {
            float wa = w2[(k + 0) * D2 + j];
            float wb = w2[(k + 1) * D2 + j];
            float wc = w2[(k + 2) * D2 + j];
            float wd = w2[(k + 3) * D2 + j];
#pragma unroll
            for (int tt = 0; tt < 20; tt++) {
                float4 s4 = *(const float4*)&sh[(tb + tt) * D2 + k];
                acc[tt] += s4.x * wa + s4.y * wb + s4.z * wc + s4.w * wd;
            }
        }
        float vj = v[j], bj = bias[j];
        const float base = lpj + bj;
#pragma unroll
        for (int tt = 0; tt < 20; tt++) {
            float x = base + acc[tt];
            float e = __expf(-x);
            cbuf[(tb + tt) * D2 + j] = __fdividef(vj, 1.f + e);
        }
    }
    __syncthreads();

    for (int t = warp; t < TT; t += 16) {
        float c = 0.f;
        for (int jj = lane; jj < D2; jj += 32) c += cbuf[t * D2 + jj];
#pragma unroll
        for (int o = 16; o > 0; o >>= 1) c += __shfl_xor_sync(0xFFFFFFFFu, c, o);
        if (lane == 0) coefs[t] = c * mask[b * TT + t];
    }
    __syncthreads();

    if (tid < D2) {
        float s = 0.f;
#pragma unroll
        for (int t = 0; t < TT; t++) s += coefs[t] * sh[t * D2 + tid];
        svec[tid] = s;
    }
    __syncthreads();

    if (j < D2) {
        const int k0 = half * DD;
        float m = 0.f;
        for (int k = k0; k < k0 + DD; k++) m += svec[k] * w3[(size_t)k * D2 + j];
        cbuf[half * D2 + j] = m;
    }
    __syncthreads();
    if (half == 0 && j < D2) {
        float m = cbuf[j] + cbuf[D2 + j];
        int pos = (j < DD) ? j : (j + 28);
        g_ma16[b * KP + pos] = __float2half(m);
    }
}

// ---------------------------------------------------------------------------
// Phase 2: logits = ma16 @ b_emb16^T, fp16 mma.m16n8k16.
// BM=256 (all batch) x BN=128 per CTA, 512 threads, grid = 1563.
// emb16 read exactly once. K=256 in 4 chunks of 64 halves, double-buffered
// cp.async. Epilogue in two 128-row halves via smem -> streaming stores.
// ---------------------------------------------------------------------------
#define CHB    128
#define ATILEB (256 * CHB)          // 32768
#define BTILEB (128 * CHB)          // 16384
#define BUFB   (ATILEB + BTILEB)    // 49152
#define SCT_OFF (2 * BUFB)          // 98304
#define P2_SMEM (SCT_OFF + 512)
#define CSTR   132

__global__ __launch_bounds__(512, 1) void phase2_impl(
    const int* __restrict__ csort,
    float* __restrict__ out)
{
    extern __shared__ __align__(16) float sm2[];
    const uint32_t sb = (uint32_t)__cvta_generic_to_shared(sm2);
    int* sct = (int*)((char*)sm2 + SCT_OFF);

    const int tid  = threadIdx.x;
    const int wid  = tid >> 5;
    const int lane = tid & 31;
    const int n0   = blockIdx.x * 128;
    const int wm = wid >> 2;    // 0..3 -> 64 batch rows each (256 total)
    const int wn = wid & 3;     // 0..3 -> 32 node cols each (128 total)

    for (int i = tid; i < 128; i += 512) {
        int n = n0 + i + 1; if (n > NNODE - 1) n = NNODE - 1;
        sct[i] = csort[n];
    }
    __syncthreads();

    const int hiA = (lane >> 4) & 1;
    const int hiB = (lane >> 3) & 1;
    int rowAoff[4], swA[4], rowBoff[2], swB[2];
#pragma unroll
    for (int mt = 0; mt < 4; mt++) {
        int r = wm * 64 + mt * 16 + (lane & 15);   // 0..255
        rowAoff[mt] = r * CHB; swA[mt] = r & 7;
    }
#pragma unroll
    for (int p = 0; p < 2; p++) {
        int r = wn * 32 + p * 16 + ((lane >> 4) & 1) * 8 + (lane & 7);
        rowBoff[p] = r * CHB; swB[p] = r & 7;
    }

    float acc[4][4][4];
#pragma unroll
    for (int mt = 0; mt < 4; mt++)
#pragma unroll
        for (int nt = 0; nt < 4; nt++)
#pragma unroll
            for (int r = 0; r < 4; r++) acc[mt][nt][r] = 0.f;

    // 3072 16-B units per chunk: A = 2048 (256 rows x 8), B = 1024 (128 x 8)
    auto issue_chunk = [&](int c) {
        const uint32_t buf = sb + (uint32_t)((c & 1) * BUFB);
#pragma unroll
        for (int i = 0; i < 6; i++) {
            int uid = tid + i * 512;
            const __half* src;
            uint32_t dst;
            if (uid < 2048) {
                int r = uid >> 3, u = uid & 7;
                dst = buf + (uint32_t)(r * CHB + ((u ^ (r & 7)) << 4));
                src = g_ma16 + (size_t)r * KP + c * 64 + u * 8;
            } else {
                int t = uid - 2048;
                int r = t >> 3, u = t & 7;
                dst = buf + (uint32_t)(ATILEB + r * CHB + ((u ^ (r & 7)) << 4));
                if (c < 2) {
                    int n = n0 + r + 1; if (n > NNODE - 1) n = NNODE - 1;
                    src = g_emb16 + (size_t)n * 128 + c * 64 + u * 8;
                } else {
                    src = g_embt16 + (size_t)sct[r] * 128 + (c - 2) * 64 + u * 8;
                }
            }
            cp16(dst, src);
        }
        cp_commit();
    };

    issue_chunk(0);
    issue_chunk(1);

#pragma unroll
    for (int c = 0; c < 4; c++) {
        if (c < 3) cp_wait<1>(); else cp_wait<0>();
        __syncthreads();

        const uint32_t bufo = (uint32_t)((c & 1) * BUFB);
#pragma unroll
        for (int ks = 0; ks < 4; ks++) {
            uint32_t af[4][4], bf[4][2];
            const int uA = 2 * ks + hiA;
            const int uB = 2 * ks + hiB;
#pragma unroll
            for (int mt = 0; mt < 4; mt++) {
                uint32_t addr = sb + bufo + (uint32_t)rowAoff[mt]
                              + (uint32_t)((uA ^ swA[mt]) << 4);
                ldsm_x4(af[mt][0], af[mt][1], af[mt][2], af[mt][3], addr);
            }
#pragma unroll
            for (int p = 0; p < 2; p++) {
                uint32_t addr = sb + bufo + (uint32_t)(ATILEB + rowBoff[p])
                              + (uint32_t)((uB ^ swB[p]) << 4);
                uint32_t r0, r1, r2, r3;
                ldsm_x4(r0, r1, r2, r3, addr);
                bf[2 * p][0] = r0;     bf[2 * p][1] = r1;
                bf[2 * p + 1][0] = r2; bf[2 * p + 1][1] = r3;
            }
#pragma unroll
            for (int mt = 0; mt < 4; mt++)
#pragma unroll
                for (int nt = 0; nt < 4; nt++)
                    mma_f16(acc[mt][nt],
                            af[mt][0], af[mt][1], af[mt][2], af[mt][3],
                            bf[nt][0], bf[nt][1]);
        }
        __syncthreads();
        if (c < 2) issue_chunk(c + 2);
    }

    // ---- epilogue: two 128-row halves through smem ----
    float* Cs = sm2;
    const bool interior = (n0 + 128 <= NOUT);
#pragma unroll
    for (int h = 0; h < 2; h++) {
        __syncthreads();
        if ((wm >> 1) == h) {
#pragma unroll
            for (int mt = 0; mt < 4; mt++) {
                int r1 = (wm & 1) * 64 + mt * 16 + (lane >> 2);
#pragma unroll
                for (int nt = 0; nt < 4; nt++) {
                    int cc = wn * 32 + nt * 8 + 2 * (lane & 3);
                    Cs[r1 * CSTR + cc]           = acc[mt][nt][0];
                    Cs[r1 * CSTR + cc + 1]       = acc[mt][nt][1];
                    Cs[(r1 + 8) * CSTR + cc]     = acc[mt][nt][2];
                    Cs[(r1 + 8) * CSTR + cc + 1] = acc[mt][nt][3];
                }
            }
        }
        __syncthreads();

        if (interior) {
            for (int idx = tid; idx < 128 * 32; idx += 512) {
                int r = idx >> 5, c4 = (idx & 31) << 2;
                float4 vv = *(const float4*)&Cs[r * CSTR + c4];
                float* po = out + (size_t)(h * 128 + r) * NOUT + n0 + c4;
                __stcs(po + 0, vv.x);
                __stcs(po + 1, vv.y);
                __stcs(po + 2, vv.z);
                __stcs(po + 3, vv.w);
            }
        } else {
            for (int idx = tid; idx < 128 * 128; idx += 512) {
                int r = idx >> 7, cc = idx & 127;
                int n = n0 + cc;
                if (n < NOUT)
                    __stcs(out + (size_t)(h * 128 + r) * NOUT + n, Cs[r * CSTR + cc]);
            }
        }
    }
}

// ---------------------------------------------------------------------------
// launch
// ---------------------------------------------------------------------------
extern "C" void kernel_launch(void* const* d_in, const int* in_sizes, int n_in,
                              void* d_out, int out_size) {
    (void)in_sizes; (void)n_in; (void)out_size;
    const float* re     = (const float*)d_in[0];
    const float* ret    = (const float*)d_in[1];
    const float* mask   = (const float*)d_in[2];
    const float* maskt  = (const float*)d_in[3];
    const int*   alias  = (const int*)d_in[4];
    const int*   aliast = (const int*)d_in[5];
    const int*   csort  = (const int*)d_in[6];
    const float* emb    = (const float*)d_in[7];
    const float* embt   = (const float*)d_in[8];
    const float* w1     = (const float*)d_in[9];
    const float* w2     = (const float*)d_in[10];
    const float* w3     = (const float*)d_in[11];
    const float* v      = (const float*)d_in[12];
    const float* bias   = (const float*)d_in[13];
    float* out = (float*)d_out;

    const size_t sm1 = (size_t)16440 * sizeof(float);   // 65,760 B
    const size_t sm2 = (size_t)P2_SMEM;                 // 98,816 B
    cudaFuncSetAttribute(fused0_kernel, cudaFuncAttributeMaxDynamicSharedMemorySize, (int)sm1);
    cudaFuncSetAttribute(phase2_impl, cudaFuncAttributeMaxDynamicSharedMemorySize, (int)sm2);

    fused0_kernel<<<BB + NPREP, 512, sm1>>>(re, ret, mask, maskt, alias, aliast,
                                            w1, w2, w3, v, bias, emb, embt);

    dim3 grid2((NOUT + 127) / 128, 1, 1);   // 1563 node tiles, BM = 256
    phase2_impl<<<grid2, 512, sm2>>>(csort, out);
}

// round 15
// speedup vs baseline: 1.3877x; 1.3877x over previous
#include <cuda_runtime.h>
#include <cuda_fp16.h>
#include <cstdint>
#include <math.h>

#define BB 256
#define TT 40
#define DD 100
#define D2 200
#define NNODE 200000
#define NTYPE 1000
#define NOUT 199999   // N_NODE - 1
#define KP 256        // padded K layout for phase 2

// device-global scratch (no allocation allowed)
__device__ __align__(16) __half g_emb16[(size_t)NNODE * 128];   // 51.2 MB
__device__ __align__(16) __half g_embt16[(size_t)NTYPE * 128];  // 256 KB
__device__ __align__(16) __half g_ma16[BB * KP];                // 128 KB

// ---------------------------------------------------------------------------
// helpers
// ---------------------------------------------------------------------------
__device__ __forceinline__ void mma_f16(float d[4],
                                        uint32_t a0, uint32_t a1, uint32_t a2, uint32_t a3,
                                        uint32_t b0, uint32_t b1) {
    asm volatile(
        "mma.sync.aligned.m16n8k16.row.col.f32.f16.f16.f32 "
        "{%0,%1,%2,%3}, {%4,%5,%6,%7}, {%8,%9}, {%0,%1,%2,%3};\n"
        : "+f"(d[0]), "+f"(d[1]), "+f"(d[2]), "+f"(d[3])
        : "r"(a0), "r"(a1), "r"(a2), "r"(a3), "r"(b0), "r"(b1));
}

__device__ __forceinline__ void ldsm_x4(uint32_t& r0, uint32_t& r1,
                                        uint32_t& r2, uint32_t& r3, uint32_t addr) {
    asm volatile("ldmatrix.sync.aligned.m8n8.x4.shared.b16 {%0,%1,%2,%3}, [%4];"
                 : "=r"(r0), "=r"(r1), "=r"(r2), "=r"(r3) : "r"(addr));
}

__device__ __forceinline__ void cp16(uint32_t dst, const void* src) {
    asm volatile("cp.async.cg.shared.global [%0], [%1], 16;"
                 :: "r"(dst), "l"(src) : "memory");
}
__device__ __forceinline__ void cp_commit() {
    asm volatile("cp.async.commit_group;" ::: "memory");
}
template <int N>
__device__ __forceinline__ void cp_wait() {
    asm volatile("cp.async.wait_group %0;" :: "n"(N) : "memory");
}

__device__ __forceinline__ uint4 h8_of(float4 a, float4 b) {
    __half2 h0 = __float22half2_rn(make_float2(a.x, a.y));
    __half2 h1 = __float22half2_rn(make_float2(a.z, a.w));
    __half2 h2 = __float22half2_rn(make_float2(b.x, b.y));
    __half2 h3 = __float22half2_rn(make_float2(b.z, b.w));
    uint4 u;
    u.x = *reinterpret_cast<uint32_t*>(&h0);
    u.y = *reinterpret_cast<uint32_t*>(&h1);
    u.z = *reinterpret_cast<uint32_t*>(&h2);
    u.w = *reinterpret_cast<uint32_t*>(&h3);
    return u;
}

// ---------------------------------------------------------------------------
// fused0: CTAs [0,256) = phase1 (one batch element each, 512 threads);
//         CTAs [256, 256+NPREP) = prep (fp32 -> fp16 padded table copies).
// (R14 component, measured ~82 us)
// ---------------------------------------------------------------------------
#define EMB_UNITS (NNODE * 16)
#define EMBT_UNITS (NTYPE * 16)
#define TOT_UNITS (EMB_UNITS + EMBT_UNITS)
#define NPREP ((TOT_UNITS + 1023) / 1024)

__global__ __launch_bounds__(512) void fused0_kernel(
    const float* __restrict__ re,     // [B,U,D]
    const float* __restrict__ ret,    // [B,U,D]
    const float* __restrict__ mask,   // [B,T]
    const float* __restrict__ maskt,  // [B,T]
    const int*   __restrict__ alias,  // [B,T]
    const int*   __restrict__ aliast, // [B,T]
    const float* __restrict__ w1,     // [2D,2D]
    const float* __restrict__ w2,     // [2D,2D]
    const float* __restrict__ w3,     // [2D,2D]
    const float* __restrict__ v,      // [2D]
    const float* __restrict__ bias,   // [2D]
    const float* __restrict__ emb,    // [N_NODE, 100]
    const float* __restrict__ embt)   // [N_TYPE, 100]
{
    const int tid = threadIdx.x;

    if (blockIdx.x >= BB) {
        // ---------------- prep path ----------------
        const int base = (blockIdx.x - BB) * 1024;
        const float4 z = make_float4(0.f, 0.f, 0.f, 0.f);
#pragma unroll
        for (int i = 0; i < 2; i++) {
            int uid = base + tid + i * 512;
            if (uid < EMB_UNITS) {
                int row = uid >> 4, u = uid & 15;
                int fb = 8 * u;
                const float4* src = (const float4*)(emb + (size_t)row * DD);
                float4 f0 = (fb < DD) ? src[fb >> 2] : z;
                float4 f1 = (fb + 4 < DD) ? src[(fb >> 2) + 1] : z;
                *(uint4*)(g_emb16 + (size_t)row * 128 + fb) = h8_of(f0, f1);
            } else if (uid < TOT_UNITS) {
                int t = uid - EMB_UNITS;
                int row = t >> 4, u = t & 15;
                int fb = 8 * u;
                const float4* src = (const float4*)(embt + (size_t)row * DD);
                float4 f0 = (fb < DD) ? src[fb >> 2] : z;
                float4 f1 = (fb + 4 < DD) ? src[(fb >> 2) + 1] : z;
                *(uint4*)(g_embt16 + (size_t)row * 128 + fb) = h8_of(f0, f1);
            }
        }
        return;
    }

    // ---------------- phase1 path ----------------
    extern __shared__ float sm1[];
    float* sh    = sm1;            // [40][200]
    float* cbuf  = sm1 + 8000;     // [40][200]
    float* coefs = sm1 + 16000;    // [40]
    float* svec  = sm1 + 16040;    // [200]
    float* lastv = sm1 + 16240;    // [200]
    __shared__ int sa[TT], sat[TT], slast[2];

    const int b = blockIdx.x;
    const int half = tid >> 8;      // 0: t 0..19, 1: t 20..39
    const int j = tid & 255;
    const int warp = tid >> 5;
    const int lane = tid & 31;

    if (tid < KP) g_ma16[b * KP + tid] = __float2half(0.f);

    if (tid < TT) {
        sa[tid]  = alias[b * TT + tid];
        sat[tid] = aliast[b * TT + tid];
    }
    if (tid == 0) {
        float s = 0.f, st = 0.f;
        for (int t = 0; t < TT; t++) { s += mask[b * TT + t]; st += maskt[b * TT + t]; }
        int rm  = (int)(s  + 0.5f); rm  = rm  < 1 ? 1 : (rm  > TT ? TT : rm);
        int rmt = (int)(st + 0.5f); rmt = rmt < 1 ? 1 : (rmt > TT ? TT : rmt);
        slast[0] = alias[b * TT + rm - 1];
        slast[1] = aliast[b * TT + rmt - 1];
    }
    __syncthreads();

    for (int idx = tid; idx < TT * D2; idx += 512) {
        int t = idx / D2, k = idx - t * D2;
        sh[idx] = (k < DD) ? re[(b * TT + sa[t]) * DD + k]
                           : ret[(b * TT + sat[t]) * DD + (k - DD)];
    }
    if (tid < D2) {
        lastv[tid] = (tid < DD) ? re[(b * TT + slast[0]) * DD + tid]
                                : ret[(b * TT + slast[1]) * DD + (tid - DD)];
    }
    __syncthreads();

    float lpj = 0.f;
    if (j < D2) {
        for (int k = 0; k < D2; k++) lpj += lastv[k] * w1[k * D2 + j];
    }

    if (j < D2) {
        const int tb = half * 20;
        float acc[20];
#pragma unroll
        for (int tt = 0; tt < 20; tt++) acc[tt] = 0.f;
        for (int k = 0; k < D2; k += 4) {
            float wa = w2[(k + 0) * D2 + j];
            float wb = w2[(k + 1) * D2 + j];
            float wc = w2[(k + 2) * D2 + j];
            float wd = w2[(k + 3) * D2 + j];
#pragma unroll
            for (int tt = 0; tt < 20; tt++) {
                float4 s4 = *(const float4*)&sh[(tb + tt) * D2 + k];
                acc[tt] += s4.x * wa + s4.y * wb + s4.z * wc + s4.w * wd;
            }
        }
        float vj = v[j], bj = bias[j];
        const float base = lpj + bj;
#pragma unroll
        for (int tt = 0; tt < 20; tt++) {
            float x = base + acc[tt];
            float e = __expf(-x);
            cbuf[(tb + tt) * D2 + j] = __fdividef(vj, 1.f + e);
        }
    }
    __syncthreads();

    for (int t = warp; t < TT; t += 16) {
        float c = 0.f;
        for (int jj = lane; jj < D2; jj += 32) c += cbuf[t * D2 + jj];
#pragma unroll
        for (int o = 16; o > 0; o >>= 1) c += __shfl_xor_sync(0xFFFFFFFFu, c, o);
        if (lane == 0) coefs[t] = c * mask[b * TT + t];
    }
    __syncthreads();

    if (tid < D2) {
        float s = 0.f;
#pragma unroll
        for (int t = 0; t < TT; t++) s += coefs[t] * sh[t * D2 + tid];
        svec[tid] = s;
    }
    __syncthreads();

    if (j < D2) {
        const int k0 = half * DD;
        float m = 0.f;
        for (int k = k0; k < k0 + DD; k++) m += svec[k] * w3[(size_t)k * D2 + j];
        cbuf[half * D2 + j] = m;
    }
    __syncthreads();
    if (half == 0 && j < D2) {
        float m = cbuf[j] + cbuf[D2 + j];
        int pos = (j < DD) ? j : (j + 28);
        g_ma16[b * KP + pos] = __float2half(m);
    }
}

// ---------------------------------------------------------------------------
// Phase 2 (exact R13 config, measured ~95 us): BM=BN=128, 256 threads,
// 2 CTAs/SM, grid (2, 1563) m-fast, K=256 in 4 chunks, double-buffered
// cp.async, XOR-swizzled smem, streaming vectorized epilogue.
// ---------------------------------------------------------------------------
#define CHB   128
#define TILEB (128 * CHB)
#define BUFB  (2 * TILEB)
#define SCT_OFF 67584
#define P2_SMEM (SCT_OFF + 512)
#define CSTR  132

__global__ __launch_bounds__(256, 2) void phase2_impl(
    const int* __restrict__ csort,
    float* __restrict__ out)
{
    extern __shared__ __align__(16) float sm2[];
    const uint32_t sb = (uint32_t)__cvta_generic_to_shared(sm2);
    int* sct = (int*)((char*)sm2 + SCT_OFF);

    const int tid  = threadIdx.x;
    const int wid  = tid >> 5;
    const int lane = tid & 31;
    const int m0   = blockIdx.x * 128;
    const int n0   = blockIdx.y * 128;
    const int wm = wid >> 2;
    const int wn = wid & 3;

    for (int i = tid; i < 128; i += 256) {
        int n = n0 + i + 1; if (n > NNODE - 1) n = NNODE - 1;
        sct[i] = csort[n];
    }
    __syncthreads();

    const int hiA = (lane >> 4) & 1;
    const int hiB = (lane >> 3) & 1;
    int rowAoff[4], swA[4], rowBoff[2], swB[2];
#pragma unroll
    for (int mt = 0; mt < 4; mt++) {
        int r = wm * 64 + mt * 16 + (lane & 15);
        rowAoff[mt] = r * CHB; swA[mt] = r & 7;
    }
#pragma unroll
    for (int p = 0; p < 2; p++) {
        int r = wn * 32 + p * 16 + ((lane >> 4) & 1) * 8 + (lane & 7);
        rowBoff[p] = r * CHB; swB[p] = r & 7;
    }

    float acc[4][4][4];
#pragma unroll
    for (int mt = 0; mt < 4; mt++)
#pragma unroll
        for (int nt = 0; nt < 4; nt++)
#pragma unroll
            for (int r = 0; r < 4; r++) acc[mt][nt][r] = 0.f;

    auto issue_chunk = [&](int c) {
        const uint32_t buf = sb + (uint32_t)((c & 1) * BUFB);
#pragma unroll
        for (int i = 0; i < 8; i++) {
            int uid = tid + i * 256;
            int tile = uid >> 10;
            int r = (uid >> 3) & 127;
            int u = uid & 7;
            uint32_t dst = buf + (uint32_t)(tile * TILEB + r * CHB
                                            + ((u ^ (r & 7)) << 4));
            const __half* src;
            if (tile == 0) {
                src = g_ma16 + (size_t)(m0 + r) * KP + c * 64 + u * 8;
            } else if (c < 2) {
                int n = n0 + r + 1; if (n > NNODE - 1) n = NNODE - 1;
                src = g_emb16 + (size_t)n * 128 + c * 64 + u * 8;
            } else {
                src = g_embt16 + (size_t)sct[r] * 128 + (c - 2) * 64 + u * 8;
            }
            cp16(dst, src);
        }
        cp_commit();
    };

    issue_chunk(0);
    issue_chunk(1);

#pragma unroll
    for (int c = 0; c < 4; c++) {
        if (c < 3) cp_wait<1>(); else cp_wait<0>();
        __syncthreads();

        const uint32_t bufo = (uint32_t)((c & 1) * BUFB);
#pragma unroll
        for (int ks = 0; ks < 4; ks++) {
            uint32_t af[4][4], bf[4][2];
            const int uA = 2 * ks + hiA;
            const int uB = 2 * ks + hiB;
#pragma unroll
            for (int mt = 0; mt < 4; mt++) {
                uint32_t addr = sb + bufo + (uint32_t)rowAoff[mt]
                              + (uint32_t)((uA ^ swA[mt]) << 4);
                ldsm_x4(af[mt][0], af[mt][1], af[mt][2], af[mt][3], addr);
            }
#pragma unroll
            for (int p = 0; p < 2; p++) {
                uint32_t addr = sb + bufo + (uint32_t)TILEB + (uint32_t)rowBoff[p]
                              + (uint32_t)((uB ^ swB[p]) << 4);
                uint32_t r0, r1, r2, r3;
                ldsm_x4(r0, r1, r2, r3, addr);
                bf[2 * p][0] = r0;     bf[2 * p][1] = r1;
                bf[2 * p + 1][0] = r2; bf[2 * p + 1][1] = r3;
            }
#pragma unroll
            for (int mt = 0; mt < 4; mt++)
#pragma unroll
                for (int nt = 0; nt < 4; nt++)
                    mma_f16(acc[mt][nt],
                            af[mt][0], af[mt][1], af[mt][2], af[mt][3],
                            bf[nt][0], bf[nt][1]);
        }
        __syncthreads();
        if (c < 2) issue_chunk(c + 2);
    }

    // epilogue: smem transpose -> streaming coalesced stores
    float* Cs = sm2;
#pragma unroll
    for (int mt = 0; mt < 4; mt++) {
        int r1 = wm * 64 + mt * 16 + (lane >> 2);
#pragma unroll
        for (int nt = 0; nt < 4; nt++) {
            int cc = wn * 32 + nt * 8 + 2 * (lane & 3);
            Cs[r1 * CSTR + cc]           = acc[mt][nt][0];
            Cs[r1 * CSTR + cc + 1]       = acc[mt][nt][1];
            Cs[(r1 + 8) * CSTR + cc]     = acc[mt][nt][2];
            Cs[(r1 + 8) * CSTR + cc + 1] = acc[mt][nt][3];
        }
    }
    __syncthreads();

    if (n0 + 128 <= NOUT) {
        for (int idx = tid; idx < 128 * 32; idx += 256) {
            int r = idx >> 5, c4 = (idx & 31) << 2;
            float4 vv = *(const float4*)&Cs[r * CSTR + c4];
            float* po = out + (size_t)(m0 + r) * NOUT + n0 + c4;
            __stcs(po + 0, vv.x);
            __stcs(po + 1, vv.y);
            __stcs(po + 2, vv.z);
            __stcs(po + 3, vv.w);
        }
    } else {
        for (int idx = tid; idx < 128 * 128; idx += 256) {
            int r = idx >> 7, cc = idx & 127;
            int n = n0 + cc;
            if (n < NOUT)
                __stcs(out + (size_t)(m0 + r) * NOUT + n, Cs[r * CSTR + cc]);
        }
    }
}

// ---------------------------------------------------------------------------
// launch
// ---------------------------------------------------------------------------
extern "C" void kernel_launch(void* const* d_in, const int* in_sizes, int n_in,
                              void* d_out, int out_size) {
    (void)in_sizes; (void)n_in; (void)out_size;
    const float* re     = (const float*)d_in[0];
    const float* ret    = (const float*)d_in[1];
    const float* mask   = (const float*)d_in[2];
    const float* maskt  = (const float*)d_in[3];
    const int*   alias  = (const int*)d_in[4];
    const int*   aliast = (const int*)d_in[5];
    const int*   csort  = (const int*)d_in[6];
    const float* emb    = (const float*)d_in[7];
    const float* embt   = (const float*)d_in[8];
    const float* w1     = (const float*)d_in[9];
    const float* w2     = (const float*)d_in[10];
    const float* w3     = (const float*)d_in[11];
    const float* v      = (const float*)d_in[12];
    const float* bias   = (const float*)d_in[13];
    float* out = (float*)d_out;

    const size_t sm1 = (size_t)16440 * sizeof(float);   // 65,760 B
    const size_t sm2 = (size_t)P2_SMEM;                 // 68,096 B
    cudaFuncSetAttribute(fused0_kernel, cudaFuncAttributeMaxDynamicSharedMemorySize, (int)sm1);
    cudaFuncSetAttribute(phase2_impl, cudaFuncAttributeMaxDynamicSharedMemorySize, (int)sm2);

    fused0_kernel<<<BB + NPREP, 512, sm1>>>(re, ret, mask, maskt, alias, aliast,
                                            w1, w2, w3, v, bias, emb, embt);

    dim3 grid2(2, (NOUT + 127) / 128, 1);   // m-fast x 1563 n-tiles
    phase2_impl<<<grid2, 256, sm2>>>(csort, out);
}

// round 16
// speedup vs baseline: 1.4490x; 1.0442x over previous
#include <cuda_runtime.h>
#include <cuda_fp16.h>
#include <cstdint>
#include <math.h>

#define BB 256
#define TT 40
#define DD 100
#define D2 200
#define NNODE 200000
#define NTYPE 1000
#define NOUT 199999   // N_NODE - 1
#define KP 256        // padded K layout for phase 2

// device-global scratch (no allocation allowed)
__device__ __align__(16) __half g_emb16[(size_t)NNODE * 128];   // 51.2 MB
__device__ __align__(16) __half g_embt16[(size_t)NTYPE * 128];  // 256 KB
__device__ __align__(16) __half g_ma16[BB * KP];                // 128 KB

// ---------------------------------------------------------------------------
// helpers
// ---------------------------------------------------------------------------
__device__ __forceinline__ void mma_f16(float d[4],
                                        uint32_t a0, uint32_t a1, uint32_t a2, uint32_t a3,
                                        uint32_t b0, uint32_t b1) {
    asm volatile(
        "mma.sync.aligned.m16n8k16.row.col.f32.f16.f16.f32 "
        "{%0,%1,%2,%3}, {%4,%5,%6,%7}, {%8,%9}, {%0,%1,%2,%3};\n"
        : "+f"(d[0]), "+f"(d[1]), "+f"(d[2]), "+f"(d[3])
        : "r"(a0), "r"(a1), "r"(a2), "r"(a3), "r"(b0), "r"(b1));
}

__device__ __forceinline__ void ldsm_x4(uint32_t& r0, uint32_t& r1,
                                        uint32_t& r2, uint32_t& r3, uint32_t addr) {
    asm volatile("ldmatrix.sync.aligned.m8n8.x4.shared.b16 {%0,%1,%2,%3}, [%4];"
                 : "=r"(r0), "=r"(r1), "=r"(r2), "=r"(r3) : "r"(addr));
}

__device__ __forceinline__ void cp16(uint32_t dst, const void* src) {
    asm volatile("cp.async.cg.shared.global [%0], [%1], 16;"
                 :: "r"(dst), "l"(src) : "memory");
}
__device__ __forceinline__ void cp_commit() {
    asm volatile("cp.async.commit_group;" ::: "memory");
}
template <int N>
__device__ __forceinline__ void cp_wait() {
    asm volatile("cp.async.wait_group %0;" :: "n"(N) : "memory");
}

__device__ __forceinline__ uint4 h8_of(float4 a, float4 b) {
    __half2 h0 = __float22half2_rn(make_float2(a.x, a.y));
    __half2 h1 = __float22half2_rn(make_float2(a.z, a.w));
    __half2 h2 = __float22half2_rn(make_float2(b.x, b.y));
    __half2 h3 = __float22half2_rn(make_float2(b.z, b.w));
    uint4 u;
    u.x = *reinterpret_cast<uint32_t*>(&h0);
    u.y = *reinterpret_cast<uint32_t*>(&h1);
    u.z = *reinterpret_cast<uint32_t*>(&h2);
    u.w = *reinterpret_cast<uint32_t*>(&h3);
    return u;
}

// ---------------------------------------------------------------------------
// fused0: CTAs [0,256) = phase1 (one batch element each, 512 threads);
//         CTAs [256, 256+NPREP) = prep (fp32 -> fp16 padded table copies).
// (measured ~80 us in R14/R15 — unchanged)
// ---------------------------------------------------------------------------
#define EMB_UNITS (NNODE * 16)
#define EMBT_UNITS (NTYPE * 16)
#define TOT_UNITS (EMB_UNITS + EMBT_UNITS)
#define NPREP ((TOT_UNITS + 1023) / 1024)

__global__ __launch_bounds__(512) void fused0_kernel(
    const float* __restrict__ re,     // [B,U,D]
    const float* __restrict__ ret,    // [B,U,D]
    const float* __restrict__ mask,   // [B,T]
    const float* __restrict__ maskt,  // [B,T]
    const int*   __restrict__ alias,  // [B,T]
    const int*   __restrict__ aliast, // [B,T]
    const float* __restrict__ w1,     // [2D,2D]
    const float* __restrict__ w2,     // [2D,2D]
    const float* __restrict__ w3,     // [2D,2D]
    const float* __restrict__ v,      // [2D]
    const float* __restrict__ bias,   // [2D]
    const float* __restrict__ emb,    // [N_NODE, 100]
    const float* __restrict__ embt)   // [N_TYPE, 100]
{
    const int tid = threadIdx.x;

    if (blockIdx.x >= BB) {
        // ---------------- prep path ----------------
        const int base = (blockIdx.x - BB) * 1024;
        const float4 z = make_float4(0.f, 0.f, 0.f, 0.f);
#pragma unroll
        for (int i = 0; i < 2; i++) {
            int uid = base + tid + i * 512;
            if (uid < EMB_UNITS) {
                int row = uid >> 4, u = uid & 15;
                int fb = 8 * u;
                const float4* src = (const float4*)(emb + (size_t)row * DD);
                float4 f0 = (fb < DD) ? src[fb >> 2] : z;
                float4 f1 = (fb + 4 < DD) ? src[(fb >> 2) + 1] : z;
                *(uint4*)(g_emb16 + (size_t)row * 128 + fb) = h8_of(f0, f1);
            } else if (uid < TOT_UNITS) {
                int t = uid - EMB_UNITS;
                int row = t >> 4, u = t & 15;
                int fb = 8 * u;
                const float4* src = (const float4*)(embt + (size_t)row * DD);
                float4 f0 = (fb < DD) ? src[fb >> 2] : z;
                float4 f1 = (fb + 4 < DD) ? src[(fb >> 2) + 1] : z;
                *(uint4*)(g_embt16 + (size_t)row * 128 + fb) = h8_of(f0, f1);
            }
        }
        return;
    }

    // ---------------- phase1 path ----------------
    extern __shared__ float sm1[];
    float* sh    = sm1;            // [40][200]
    float* cbuf  = sm1 + 8000;     // [40][200]
    float* coefs = sm1 + 16000;    // [40]
    float* svec  = sm1 + 16040;    // [200]
    float* lastv = sm1 + 16240;    // [200]
    __shared__ int sa[TT], sat[TT], slast[2];

    const int b = blockIdx.x;
    const int half = tid >> 8;      // 0: t 0..19, 1: t 20..39
    const int j = tid & 255;
    const int warp = tid >> 5;
    const int lane = tid & 31;

    if (tid < KP) g_ma16[b * KP + tid] = __float2half(0.f);

    if (tid < TT) {
        sa[tid]  = alias[b * TT + tid];
        sat[tid] = aliast[b * TT + tid];
    }
    if (tid == 0) {
        float s = 0.f, st = 0.f;
        for (int t = 0; t < TT; t++) { s += mask[b * TT + t]; st += maskt[b * TT + t]; }
        int rm  = (int)(s  + 0.5f); rm  = rm  < 1 ? 1 : (rm  > TT ? TT : rm);
        int rmt = (int)(st + 0.5f); rmt = rmt < 1 ? 1 : (rmt > TT ? TT : rmt);
        slast[0] = alias[b * TT + rm - 1];
        slast[1] = aliast[b * TT + rmt - 1];
    }
    __syncthreads();

    for (int idx = tid; idx < TT * D2; idx += 512) {
        int t = idx / D2, k = idx - t * D2;
        sh[idx] = (k < DD) ? re[(b * TT + sa[t]) * DD + k]
                           : ret[(b * TT + sat[t]) * DD + (k - DD)];
    }
    if (tid < D2) {
        lastv[tid] = (tid < DD) ? re[(b * TT + slast[0]) * DD + tid]
                                : ret[(b * TT + slast[1]) * DD + (tid - DD)];
    }
    __syncthreads();

    float lpj = 0.f;
    if (j < D2) {
        for (int k = 0; k < D2; k++) lpj += lastv[k] * w1[k * D2 + j];
    }

    if (j < D2) {
        const int tb = half * 20;
        float acc[20];
#pragma unroll
        for (int tt = 0; tt < 20; tt++) acc[tt] = 0.f;
        for (int k = 0; k < D2; k += 4) {
            float wa = w2[(k + 0) * D2 + j];
            float wb = w2[(k + 1) * D2 + j];
            float wc = w2[(k + 2) * D2 + j];
            float wd = w2[(k + 3) * D2 + j];
#pragma unroll
            for (int tt = 0; tt < 20; tt++) {
                float4 s4 = *(const float4*)&sh[(tb + tt) * D2 + k];
                acc[tt] += s4.x * wa + s4.y * wb + s4.z * wc + s4.w * wd;
            }
        }
        float vj = v[j], bj = bias[j];
        const float base = lpj + bj;
#pragma unroll
        for (int tt = 0; tt < 20; tt++) {
            float x = base + acc[tt];
            float e = __expf(-x);
            cbuf[(tb + tt) * D2 + j] = __fdividef(vj, 1.f + e);
        }
    }
    __syncthreads();

    for (int t = warp; t < TT; t += 16) {
        float c = 0.f;
        for (int jj = lane; jj < D2; jj += 32) c += cbuf[t * D2 + jj];
#pragma unroll
        for (int o = 16; o > 0; o >>= 1) c += __shfl_xor_sync(0xFFFFFFFFu, c, o);
        if (lane == 0) coefs[t] = c * mask[b * TT + t];
    }
    __syncthreads();

    if (tid < D2) {
        float s = 0.f;
#pragma unroll
        for (int t = 0; t < TT; t++) s += coefs[t] * sh[t * D2 + tid];
        svec[tid] = s;
    }
    __syncthreads();

    if (j < D2) {
        const int k0 = half * DD;
        float m = 0.f;
        for (int k = k0; k < k0 + DD; k++) m += svec[k] * w3[(size_t)k * D2 + j];
        cbuf[half * D2 + j] = m;
    }
    __syncthreads();
    if (half == 0 && j < D2) {
        float m = cbuf[j] + cbuf[D2 + j];
        int pos = (j < DD) ? j : (j + 28);
        g_ma16[b * KP + pos] = __float2half(m);
    }
}

// ---------------------------------------------------------------------------
// Phase 2: BM=BN=128, 256 threads, 2 CTAs/SM, grid (2, 1563) m-fast.
// K=256 in 4 chunks; 3-deep cp.async pipeline (3 x 32KB buffers).
// Epilogue: rotation-aligned smem transpose -> STG.128 streaming stores.
// ---------------------------------------------------------------------------
#define CHB   128
#define TILEB (128 * CHB)          // 16384 per operand tile per chunk
#define BUFB  (2 * TILEB)          // 32768 per (A,B) stage buffer
#define SCT_OFF (3 * BUFB)         // 98304
#define P2_SMEM (SCT_OFF + 512)    // 98816
#define CSTR  132

__global__ __launch_bounds__(256, 2) void phase2_impl(
    const int* __restrict__ csort,
    float* __restrict__ out)
{
    extern __shared__ __align__(16) float sm2[];
    const uint32_t sb = (uint32_t)__cvta_generic_to_shared(sm2);
    int* sct = (int*)((char*)sm2 + SCT_OFF);

    const int tid  = threadIdx.x;
    const int wid  = tid >> 5;
    const int lane = tid & 31;
    const int m0   = blockIdx.x * 128;
    const int n0   = blockIdx.y * 128;
    const int wm = wid >> 2;
    const int wn = wid & 3;

    for (int i = tid; i < 128; i += 256) {
        int n = n0 + i + 1; if (n > NNODE - 1) n = NNODE - 1;
        sct[i] = csort[n];
    }
    __syncthreads();

    const int hiA = (lane >> 4) & 1;
    const int hiB = (lane >> 3) & 1;
    int rowAoff[4], swA[4], rowBoff[2], swB[2];
#pragma unroll
    for (int mt = 0; mt < 4; mt++) {
        int r = wm * 64 + mt * 16 + (lane & 15);
        rowAoff[mt] = r * CHB; swA[mt] = r & 7;
    }
#pragma unroll
    for (int p = 0; p < 2; p++) {
        int r = wn * 32 + p * 16 + ((lane >> 4) & 1) * 8 + (lane & 7);
        rowBoff[p] = r * CHB; swB[p] = r & 7;
    }

    float acc[4][4][4];
#pragma unroll
    for (int mt = 0; mt < 4; mt++)
#pragma unroll
        for (int nt = 0; nt < 4; nt++)
#pragma unroll
            for (int r = 0; r < 4; r++) acc[mt][nt][r] = 0.f;

    auto issue_chunk = [&](int c) {
        const int cb = (c < 3) ? c : (c - 3);
        const uint32_t buf = sb + (uint32_t)(cb * BUFB);
#pragma unroll
        for (int i = 0; i < 8; i++) {
            int uid = tid + i * 256;
            int tile = uid >> 10;
            int r = (uid >> 3) & 127;
            int u = uid & 7;
            uint32_t dst = buf + (uint32_t)(tile * TILEB + r * CHB
                                            + ((u ^ (r & 7)) << 4));
            const __half* src;
            if (tile == 0) {
                src = g_ma16 + (size_t)(m0 + r) * KP + c * 64 + u * 8;
            } else if (c < 2) {
                int n = n0 + r + 1; if (n > NNODE - 1) n = NNODE - 1;
                src = g_emb16 + (size_t)n * 128 + c * 64 + u * 8;
            } else {
                src = g_embt16 + (size_t)sct[r] * 128 + (c - 2) * 64 + u * 8;
            }
            cp16(dst, src);
        }
        cp_commit();
    };

    issue_chunk(0);
    issue_chunk(1);
    issue_chunk(2);

#pragma unroll
    for (int c = 0; c < 4; c++) {
        if (c <= 1)      cp_wait<2>();
        else if (c == 2) cp_wait<1>();
        else             cp_wait<0>();
        __syncthreads();

        const int cb = (c < 3) ? c : (c - 3);
        const uint32_t bufo = (uint32_t)(cb * BUFB);
#pragma unroll
        for (int ks = 0; ks < 4; ks++) {
            uint32_t af[4][4], bf[4][2];
            const int uA = 2 * ks + hiA;
            const int uB = 2 * ks + hiB;
#pragma unroll
            for (int mt = 0; mt < 4; mt++) {
                uint32_t addr = sb + bufo + (uint32_t)rowAoff[mt]
                              + (uint32_t)((uA ^ swA[mt]) << 4);
                ldsm_x4(af[mt][0], af[mt][1], af[mt][2], af[mt][3], addr);
            }
#pragma unroll
            for (int p = 0; p < 2; p++) {
                uint32_t addr = sb + bufo + (uint32_t)TILEB + (uint32_t)rowBoff[p]
                              + (uint32_t)((uB ^ swB[p]) << 4);
                uint32_t r0, r1, r2, r3;
                ldsm_x4(r0, r1, r2, r3, addr);
                bf[2 * p][0] = r0;     bf[2 * p][1] = r1;
                bf[2 * p + 1][0] = r2; bf[2 * p + 1][1] = r3;
            }
#pragma unroll
            for (int mt = 0; mt < 4; mt++)
#pragma unroll
                for (int nt = 0; nt < 4; nt++)
                    mma_f16(acc[mt][nt],
                            af[mt][0], af[mt][1], af[mt][2], af[mt][3],
                            bf[nt][0], bf[nt][1]);
        }
        __syncthreads();
        if (c == 0) issue_chunk(3);
    }

    // ---- epilogue ----
    float* Cs = sm2;
    if (n0 + 128 <= NOUT) {
        // Rotation-aligned: slot = (cc - sh_row) & 127 so each output row's
        // 16B-aligned span starts at slot 0. sh = (4 - ((3*R + n0)&3)) & 3
        // (since NOUT % 4 == 3).
#pragma unroll
        for (int mt = 0; mt < 4; mt++) {
            int r1 = wm * 64 + mt * 16 + (lane >> 2);
            int r2 = r1 + 8;
            int sh1 = (4 - ((3 * (m0 + r1) + n0) & 3)) & 3;
            int sh2 = (4 - ((3 * (m0 + r2) + n0) & 3)) & 3;
#pragma unroll
            for (int nt = 0; nt < 4; nt++) {
                int cc = wn * 32 + nt * 8 + 2 * (lane & 3);
                Cs[r1 * CSTR + ((cc     - sh1) & 127)] = acc[mt][nt][0];
                Cs[r1 * CSTR + ((cc + 1 - sh1) & 127)] = acc[mt][nt][1];
                Cs[r2 * CSTR + ((cc     - sh2) & 127)] = acc[mt][nt][2];
                Cs[r2 * CSTR + ((cc + 1 - sh2) & 127)] = acc[mt][nt][3];
            }
        }
        __syncthreads();

        // one warp per row: 31 aligned STG.128 + lane31 handles 4 wrapped
        // head/tail scalars (slots 124..127 <-> columns (slot+sh)&127)
#pragma unroll
        for (int it = 0; it < 16; it++) {
            int r = wid + (it << 3);
            size_t g0 = (size_t)(m0 + r) * NOUT + n0;
            int sh = (4 - ((3 * (m0 + r) + n0) & 3)) & 3;
            if (lane < 31) {
                float4 vv = *(const float4*)&Cs[r * CSTR + 4 * lane];
                __stcs((float4*)(out + g0 + sh + 4 * lane), vv);
            } else {
#pragma unroll
                for (int i2 = 0; i2 < 4; i2++) {
                    int s = 124 + i2;
                    int col = (s + sh) & 127;
                    __stcs(out + g0 + col, Cs[r * CSTR + s]);
                }
            }
        }
    } else {
        // edge n-tile: plain transpose + guarded scalar stores
#pragma unroll
        for (int mt = 0; mt < 4; mt++) {
            int r1 = wm * 64 + mt * 16 + (lane >> 2);
#pragma unroll
            for (int nt = 0; nt < 4; nt++) {
                int cc = wn * 32 + nt * 8 + 2 * (lane & 3);
                Cs[r1 * CSTR + cc]           = acc[mt][nt][0];
                Cs[r1 * CSTR + cc + 1]       = acc[mt][nt][1];
                Cs[(r1 + 8) * CSTR + cc]     = acc[mt][nt][2];
                Cs[(r1 + 8) * CSTR + cc + 1] = acc[mt][nt][3];
            }
        }
        __syncthreads();
        for (int idx = tid; idx < 128 * 128; idx += 256) {
            int r = idx >> 7, cc = idx & 127;
            int n = n0 + cc;
            if (n < NOUT)
                __stcs(out + (size_t)(m0 + r) * NOUT + n, Cs[r * CSTR + cc]);
        }
    }
}

// ---------------------------------------------------------------------------
// launch
// ---------------------------------------------------------------------------
extern "C" void kernel_launch(void* const* d_in, const int* in_sizes, int n_in,
                              void* d_out, int out_size) {
    (void)in_sizes; (void)n_in; (void)out_size;
    const float* re     = (const float*)d_in[0];
    const float* ret    = (const float*)d_in[1];
    const float* mask   = (const float*)d_in[2];
    const float* maskt  = (const float*)d_in[3];
    const int*   alias  = (const int*)d_in[4];
    const int*   aliast = (const int*)d_in[5];
    const int*   csort  = (const int*)d_in[6];
    const float* emb    = (const float*)d_in[7];
    const float* embt   = (const float*)d_in[8];
    const float* w1     = (const float*)d_in[9];
    const float* w2     = (const float*)d_in[10];
    const float* w3     = (const float*)d_in[11];
    const float* v      = (const float*)d_in[12];
    const float* bias   = (const float*)d_in[13];
    float* out = (float*)d_out;

    const size_t sm1 = (size_t)16440 * sizeof(float);   // 65,760 B
    const size_t sm2 = (size_t)P2_SMEM;                 // 98,816 B
    cudaFuncSetAttribute(fused0_kernel, cudaFuncAttributeMaxDynamicSharedMemorySize, (int)sm1);
    cudaFuncSetAttribute(phase2_impl, cudaFuncAttributeMaxDynamicSharedMemorySize, (int)sm2);

    fused0_kernel<<<BB + NPREP, 512, sm1>>>(re, ret, mask, maskt, alias, aliast,
                                            w1, w2, w3, v, bias, emb, embt);

    dim3 grid2(2, (NOUT + 127) / 128, 1);   // m-fast x 1563 n-tiles
    phase2_impl<<<grid2, 256, sm2>>>(csort, out);
}